// round 4
// baseline (speedup 1.0000x reference)
#include <cuda_runtime.h>
#include <cuda_bf16.h>

// Problem: out[8192,4096] = x[8192,4096] @ tanh(blocks * mask)
// blocks is block-diagonal: 16 blocks of 256x256. So this is 16 independent
// GEMMs: out[:, b*256:(b+1)*256] = x[:, b*256:(b+1)*256] @ tanh(B_b).
//
// Stage 1: compact + tanh the 16 diagonal blocks into a __device__ scratch
//          (4 MB), layout g_B[b][k][n] row-major in n.
// Stage 2: tiled FP32 SGEMM per (M-tile, N-tile) where each N-tile lives
//          entirely inside one diagonal block (BN=128, block size 256).

#define LAYER 4096
#define NROWS 8192
#define NBLK  16
#define BSZ   256

#define BM 128
#define BN 128
#define BK 16
#define TM 8
#define TN 8

__device__ float g_B[NBLK * BSZ * BSZ];  // 4 MB scratch: tanh'd diagonal blocks

__global__ __launch_bounds__(256) void tanh_blocks_kernel(const float* __restrict__ blocks) {
    int idx = blockIdx.x * blockDim.x + threadIdx.x;  // < 16*256*256 = 1048576
    int b = idx >> 16;          // block id
    int r = (idx >> 8) & 255;   // row within block
    int c = idx & 255;          // col within block
    // source element: blocks[b*256 + r][b*256 + c]  (mask==1 there; tanh(0)=0 elsewhere)
    float v = blocks[(size_t)(b * BSZ + r) * LAYER + (size_t)(b * BSZ + c)];
    g_B[idx] = tanhf(v);
}

__global__ __launch_bounds__(256) void bd_gemm_kernel(const float* __restrict__ x,
                                                      float* __restrict__ out) {
    const int mTile = blockIdx.y;                 // 0..63   (8192/128)
    const int nTile = blockIdx.x;                 // 0..31   (4096/128)
    const int blk   = (nTile * BN) / BSZ;         // diagonal block id (BN=128 < 256, so tile is inside one block)
    const int nInBlk = (nTile * BN) % BSZ;        // 0 or 128

    __shared__ float As[BK][BM + 4];              // A stored transposed: As[k][m]; +4 pad kills store conflicts
    __shared__ float Bs[BK][BN];

    const float* Bsrc = g_B + (size_t)blk * BSZ * BSZ;                      // [k][n], row length 256
    const float* Asrc = x + (size_t)mTile * BM * LAYER + (size_t)blk * BSZ; // x[mBase + r][blk*256 + k]

    const int tid = threadIdx.x;

    // A tile loads: BM(128) x BK(16) floats = 512 float4; 256 threads -> 2 rounds
    const int aRow  = tid >> 2;      // 0..63
    const int aCol4 = tid & 3;       // float4 index along K (4 per row)

    // B tile loads: BK(16) x BN(128) floats = 512 float4; 2 rounds
    const int bRow  = tid >> 5;      // 0..7
    const int bCol4 = tid & 31;      // float4 index along N

    // 16x16 thread grid; each thread owns an 8x8 micro-tile
    const int tRow = (tid >> 4) * TM;
    const int tCol = (tid & 15) * TN;

    float acc[TM][TN];
    #pragma unroll
    for (int i = 0; i < TM; i++)
        #pragma unroll
        for (int j = 0; j < TN; j++) acc[i][j] = 0.0f;

    float regM[TM], regN[TN];

    for (int k0 = 0; k0 < BSZ; k0 += BK) {
        // ---- load A tile (transpose into As[k][m]) ----
        #pragma unroll
        for (int r = 0; r < BM; r += 64) {
            float4 v = *reinterpret_cast<const float4*>(
                Asrc + (size_t)(aRow + r) * LAYER + k0 + aCol4 * 4);
            As[aCol4 * 4 + 0][aRow + r] = v.x;
            As[aCol4 * 4 + 1][aRow + r] = v.y;
            As[aCol4 * 4 + 2][aRow + r] = v.z;
            As[aCol4 * 4 + 3][aRow + r] = v.w;
        }
        // ---- load B tile ----
        #pragma unroll
        for (int r = 0; r < BK; r += 8) {
            float4 v = *reinterpret_cast<const float4*>(
                Bsrc + (size_t)(k0 + bRow + r) * BSZ + nInBlk + bCol4 * 4);
            *reinterpret_cast<float4*>(&Bs[bRow + r][bCol4 * 4]) = v;
        }
        __syncthreads();

        // ---- compute ----
        #pragma unroll
        for (int k = 0; k < BK; k++) {
            #pragma unroll
            for (int i = 0; i < TM; i++) regM[i] = As[k][tRow + i];
            #pragma unroll
            for (int j = 0; j < TN; j++) regN[j] = Bs[k][tCol + j];
            #pragma unroll
            for (int i = 0; i < TM; i++)
                #pragma unroll
                for (int j = 0; j < TN; j++)
                    acc[i][j] = fmaf(regM[i], regN[j], acc[i][j]);
        }
        __syncthreads();
    }

    // ---- write out ----
    float* Odst = out + (size_t)mTile * BM * LAYER + (size_t)nTile * BN;
    #pragma unroll
    for (int i = 0; i < TM; i++) {
        #pragma unroll
        for (int j = 0; j < TN; j += 4) {
            float4 v = make_float4(acc[i][j], acc[i][j + 1], acc[i][j + 2], acc[i][j + 3]);
            *reinterpret_cast<float4*>(Odst + (size_t)(tRow + i) * LAYER + tCol + j) = v;
        }
    }
}

extern "C" void kernel_launch(void* const* d_in, const int* in_sizes, int n_in,
                              void* d_out, int out_size) {
    const float* x      = (const float*)d_in[0];   // [8192, 4096] fp32
    const float* blocks = (const float*)d_in[1];   // [4096, 4096] fp32 (block-diagonal)
    // d_in[2] = mask (bool) — structure is known statically, unused.
    float* out = (float*)d_out;                    // [8192, 4096] fp32

    (void)in_sizes; (void)n_in; (void)out_size;

    // Stage 1: tanh-compact the 16 diagonal blocks (1M elements)
    tanh_blocks_kernel<<<(NBLK * BSZ * BSZ) / 256, 256>>>(blocks);

    // Stage 2: block-diagonal GEMM
    dim3 grid(LAYER / BN, NROWS / BM);  // (32, 64)
    bd_gemm_kernel<<<grid, 256>>>(x, out);
}

// round 7
// speedup vs baseline: 2.2791x; 2.2791x over previous
#include <cuda_runtime.h>
#include <cuda_bf16.h>
#include <mma.h>
#include <cstdint>

using namespace nvcuda;

// out[8192,4096] = x[8192,4096] @ tanh(blocks*mask); blocks = 16 diag blocks 256x256.
// Tensor path via warp-level wmma (HMMA, non-arch-specific PTX — tcgen05 is
// unavailable because the harness PTX target is sm_103 without the 'a' suffix).
// bf16 3-term split: out ≈ xh·Bh + xh·Bl + xl·Bh with fp32 accumulators.
//   Stage 1: tanh + hi/lo split + transpose blocks -> g_Bh/g_Bl [blk][n][k] bf16.
//   Stage 2: 128x128 CTA tile, K=256 in 4 chunks of 64, wmma m16n16k16.

#define LAYER 4096
#define NROWS 8192
#define NBLK  16
#define BSZ   256
#define KCH   64

#define LDA 72   // bf16 elements, 16-byte-aligned row stride with 8-elem pad
#define LDB 72

__device__ __align__(16) __nv_bfloat16 g_Bh[NBLK * BSZ * BSZ];  // [blk][n][k]
__device__ __align__(16) __nv_bfloat16 g_Bl[NBLK * BSZ * BSZ];

__device__ __forceinline__ uint32_t pack_bf2(__nv_bfloat16 a, __nv_bfloat16 b) {
    return (uint32_t)__bfloat16_as_ushort(a) | ((uint32_t)__bfloat16_as_ushort(b) << 16);
}

// ---------------- Stage 1: tanh + split + transpose blocks ----------------
__global__ __launch_bounds__(256) void prep_B(const float* __restrict__ blocks) {
    __shared__ float v[32][BSZ + 1];
    const int kt  = blockIdx.x;   // 0..7 (k-tile of 32)
    const int blk = blockIdx.y;   // 0..15
    const int tid = threadIdx.x;

    #pragma unroll
    for (int i = 0; i < 32; i++) {
        int idx = tid + i * 256;
        int k = idx >> 8, n = idx & 255;
        v[k][n] = blocks[(size_t)(blk * BSZ + kt * 32 + k) * LAYER + (size_t)(blk * BSZ + n)];
    }
    __syncthreads();

    const int n = tid;
    uint32_t wh[16], wl[16];
    #pragma unroll
    for (int k2 = 0; k2 < 16; k2++) {
        float t0 = tanhf(v[2 * k2][n]);
        float t1 = tanhf(v[2 * k2 + 1][n]);
        __nv_bfloat16 h0 = __float2bfloat16(t0);
        __nv_bfloat16 h1 = __float2bfloat16(t1);
        __nv_bfloat16 l0 = __float2bfloat16(t0 - __bfloat162float(h0));
        __nv_bfloat16 l1 = __float2bfloat16(t1 - __bfloat162float(h1));
        wh[k2] = pack_bf2(h0, h1);
        wl[k2] = pack_bf2(l0, l1);
    }
    size_t base = (size_t)(blk * BSZ + n) * BSZ + kt * 32;  // [blk][n][k]
    #pragma unroll
    for (int q = 0; q < 4; q++) {
        *reinterpret_cast<uint4*>(&g_Bh[base + q * 8]) =
            make_uint4(wh[4 * q], wh[4 * q + 1], wh[4 * q + 2], wh[4 * q + 3]);
        *reinterpret_cast<uint4*>(&g_Bl[base + q * 8]) =
            make_uint4(wl[4 * q], wl[4 * q + 1], wl[4 * q + 2], wl[4 * q + 3]);
    }
}

// ---------------- Stage 2: wmma GEMM ----------------
// dyn smem bytes: AH[128*LDA], AL, BH[128*LDB], BL  (bf16 each)
#define SM_AH 0
#define SM_AL (SM_AH + 128 * LDA * 2)          // 18432
#define SM_BH (SM_AL + 128 * LDA * 2)          // 36864
#define SM_BL (SM_BH + 128 * LDB * 2)          // 55296
#define SM_TOTAL (SM_BL + 128 * LDB * 2)       // 73728

__global__ void __launch_bounds__(256, 2) bd_wmma(const float* __restrict__ x,
                                                  float* __restrict__ out) {
    extern __shared__ __align__(16) char smem[];
    __nv_bfloat16* sAH = reinterpret_cast<__nv_bfloat16*>(smem + SM_AH);
    __nv_bfloat16* sAL = reinterpret_cast<__nv_bfloat16*>(smem + SM_AL);
    __nv_bfloat16* sBH = reinterpret_cast<__nv_bfloat16*>(smem + SM_BH);
    __nv_bfloat16* sBL = reinterpret_cast<__nv_bfloat16*>(smem + SM_BL);

    const int tid    = threadIdx.x;
    const int wid    = tid >> 5;
    const int warpM  = wid >> 1;            // 0..3  -> 32-row band
    const int warpN  = wid & 1;             // 0..1  -> 64-col band
    const int mTile  = blockIdx.x;          // 0..63
    const int nTile  = blockIdx.y;          // 0..31
    const int blk    = nTile >> 1;          // diagonal block
    const int nInBlk = (nTile & 1) * 128;

    const float* Asrc = x + (size_t)mTile * 128 * LAYER + (size_t)blk * BSZ;
    const __nv_bfloat16* Bh = g_Bh + (size_t)blk * BSZ * BSZ + (size_t)nInBlk * BSZ;
    const __nv_bfloat16* Bl = g_Bl + (size_t)blk * BSZ * BSZ + (size_t)nInBlk * BSZ;

    wmma::fragment<wmma::accumulator, 16, 16, 16, float> acc[2][4];
    #pragma unroll
    for (int i = 0; i < 2; i++)
        #pragma unroll
        for (int j = 0; j < 4; j++) wmma::fill_fragment(acc[i][j], 0.0f);

    for (int c = 0; c < 4; c++) {
        // ---- A chunk: 128 rows x 64 k fp32 -> bf16 hi/lo in smem ----
        #pragma unroll
        for (int i = 0; i < 8; i++) {
            int f = tid + i * 256;            // 2048 float4 ids
            int row = f >> 4, c4 = f & 15;    // 16 float4 per row
            float4 v = *reinterpret_cast<const float4*>(
                Asrc + (size_t)row * LAYER + c * KCH + c4 * 4);
            __nv_bfloat16 h0 = __float2bfloat16(v.x), h1 = __float2bfloat16(v.y),
                          h2 = __float2bfloat16(v.z), h3 = __float2bfloat16(v.w);
            __nv_bfloat16 l0 = __float2bfloat16(v.x - __bfloat162float(h0));
            __nv_bfloat16 l1 = __float2bfloat16(v.y - __bfloat162float(h1));
            __nv_bfloat16 l2 = __float2bfloat16(v.z - __bfloat162float(h2));
            __nv_bfloat16 l3 = __float2bfloat16(v.w - __bfloat162float(h3));
            int off = row * LDA + c4 * 4;     // element offset
            *reinterpret_cast<uint2*>(sAH + off) = make_uint2(pack_bf2(h0, h1), pack_bf2(h2, h3));
            *reinterpret_cast<uint2*>(sAL + off) = make_uint2(pack_bf2(l0, l1), pack_bf2(l2, l3));
        }
        // ---- B chunk: 128 n x 64 k bf16 (pre-split) -> smem col-major (k fast) ----
        #pragma unroll
        for (int i = 0; i < 4; i++) {
            int u = tid + i * 256;            // 1024 uint4 ids
            int n = u >> 3, q = u & 7;        // 8 uint4 (of 8 bf16) per n-row
            int off = n * LDB + q * 8;        // element (k = q*8, n) at k + n*LDB
            *reinterpret_cast<uint4*>(sBH + off) =
                *reinterpret_cast<const uint4*>(Bh + (size_t)n * BSZ + c * KCH + q * 8);
            *reinterpret_cast<uint4*>(sBL + off) =
                *reinterpret_cast<const uint4*>(Bl + (size_t)n * BSZ + c * KCH + q * 8);
        }
        __syncthreads();

        // ---- compute 4 k16 steps ----
        #pragma unroll
        for (int ks = 0; ks < 4; ks++) {
            wmma::fragment<wmma::matrix_a, 16, 16, 16, __nv_bfloat16, wmma::row_major> a_h[2], a_l[2];
            wmma::fragment<wmma::matrix_b, 16, 16, 16, __nv_bfloat16, wmma::col_major> b[4];

            #pragma unroll
            for (int i = 0; i < 2; i++) {
                const int r0 = warpM * 32 + i * 16;
                wmma::load_matrix_sync(a_h[i], sAH + r0 * LDA + ks * 16, LDA);
                wmma::load_matrix_sync(a_l[i], sAL + r0 * LDA + ks * 16, LDA);
            }
            // b_h live: do hh + lh
            #pragma unroll
            for (int j = 0; j < 4; j++) {
                const int n0 = warpN * 64 + j * 16;
                wmma::load_matrix_sync(b[j], sBH + ks * 16 + n0 * LDB, LDB);
            }
            #pragma unroll
            for (int i = 0; i < 2; i++)
                #pragma unroll
                for (int j = 0; j < 4; j++) {
                    wmma::mma_sync(acc[i][j], a_h[i], b[j], acc[i][j]);
                    wmma::mma_sync(acc[i][j], a_l[i], b[j], acc[i][j]);
                }
            // reuse b frags for b_l: do hl
            #pragma unroll
            for (int j = 0; j < 4; j++) {
                const int n0 = warpN * 64 + j * 16;
                wmma::load_matrix_sync(b[j], sBL + ks * 16 + n0 * LDB, LDB);
            }
            #pragma unroll
            for (int i = 0; i < 2; i++)
                #pragma unroll
                for (int j = 0; j < 4; j++)
                    wmma::mma_sync(acc[i][j], a_h[i], b[j], acc[i][j]);
        }
        __syncthreads();
    }

    // ---- epilogue: direct fp32 stores ----
    #pragma unroll
    for (int i = 0; i < 2; i++) {
        const int row0 = mTile * 128 + warpM * 32 + i * 16;
        #pragma unroll
        for (int j = 0; j < 4; j++) {
            const int col0 = nTile * 128 + warpN * 64 + j * 16;
            wmma::store_matrix_sync(out + (size_t)row0 * LAYER + col0, acc[i][j],
                                    LAYER, wmma::mem_row_major);
        }
    }
}

// ---------------- launch ----------------
extern "C" void kernel_launch(void* const* d_in, const int* in_sizes, int n_in,
                              void* d_out, int out_size) {
    const float* x      = (const float*)d_in[0];
    const float* blocks = (const float*)d_in[1];
    float* out = (float*)d_out;
    (void)in_sizes; (void)n_in; (void)out_size;

    cudaFuncSetAttribute(bd_wmma, cudaFuncAttributeMaxDynamicSharedMemorySize, SM_TOTAL);

    prep_B<<<dim3(8, NBLK), 256>>>(blocks);
    bd_wmma<<<dim3(NROWS / 128, LAYER / 128), 256, SM_TOTAL>>>(x, out);
}

// round 8
// speedup vs baseline: 4.9495x; 2.1717x over previous
#include <cuda_runtime.h>
#include <cuda_fp16.h>
#include <mma.h>
#include <cstdint>

using namespace nvcuda;

// out[8192,4096] = x[8192,4096] @ tanh(blocks*mask); blocks = 16 diag blocks 256x256.
// fp16 single-pass HMMA (norm rel-err ~4e-4 < 1e-3 threshold):
//   Stage 1: tanh + transpose blocks -> g_B [blk][n][k] fp16.
//   Stage 2: CTA tile 128x256 (full block N), K=256 in 4 chunks of 64,
//            double-buffered smem; B via cp.async, A prefetched in regs and
//            converted fp32->fp16 in-kernel. 512 threads, warp grid 4M x 4N.

#define LAYER 4096
#define NROWS 8192
#define NBLK  16
#define BSZ   256
#define KCH   64
#define LDA   72   // fp16 elems; row stride 144 B (16B-aligned, conflict-staggered)
#define LDB   72

__device__ __align__(16) __half g_B[NBLK * BSZ * BSZ];  // [blk][n][k]

__device__ __forceinline__ uint32_t smem_u32(const void* p) {
    uint32_t a;
    asm("{ .reg .u64 t; cvta.to.shared.u64 t, %1; cvt.u32.u64 %0, t; }" : "=r"(a) : "l"(p));
    return a;
}
__device__ __forceinline__ uint32_t h2u(__half2 h) {
    return *reinterpret_cast<uint32_t*>(&h);
}

// ---------------- Stage 1: tanh + transpose blocks ----------------
__global__ __launch_bounds__(256) void prep_B(const float* __restrict__ blocks) {
    __shared__ float v[32][BSZ + 1];
    const int kt  = blockIdx.x;   // 0..7
    const int blk = blockIdx.y;   // 0..15
    const int tid = threadIdx.x;

    #pragma unroll
    for (int i = 0; i < 32; i++) {
        int idx = tid + i * 256;
        int k = idx >> 8, n = idx & 255;
        v[k][n] = blocks[(size_t)(blk * BSZ + kt * 32 + k) * LAYER + (size_t)(blk * BSZ + n)];
    }
    __syncthreads();

    const int n = tid;
    uint32_t w[16];
    #pragma unroll
    for (int k2 = 0; k2 < 16; k2++) {
        float t0 = tanhf(v[2 * k2][n]);
        float t1 = tanhf(v[2 * k2 + 1][n]);
        w[k2] = h2u(__floats2half2_rn(t0, t1));
    }
    size_t base = (size_t)(blk * BSZ + n) * BSZ + kt * 32;  // [blk][n][k]
    #pragma unroll
    for (int q = 0; q < 4; q++)
        *reinterpret_cast<uint4*>(&g_B[base + q * 8]) =
            make_uint4(w[4 * q], w[4 * q + 1], w[4 * q + 2], w[4 * q + 3]);
}

// ---------------- Stage 2: pipelined HMMA GEMM ----------------
// dyn smem: buf0 {A:18432 B, B:36864 B}, buf1 same  -> 110592 B total
#define SMA0 0
#define SMB0 18432
#define SMA1 55296
#define SMB1 73728
#define SM_TOTAL 110592

__global__ void __launch_bounds__(512, 1) bd_hmma(const float* __restrict__ x,
                                                  float* __restrict__ out) {
    extern __shared__ __align__(16) char smem[];
    const uint32_t sbase = smem_u32(smem);
    const int tid = threadIdx.x;
    const int w   = tid >> 5;
    const int wm  = w & 3;        // 0..3 -> 32-row band
    const int wn  = w >> 2;       // 0..3 -> 64-col band
    const int mTile = blockIdx.x; // 0..63
    const int blk   = blockIdx.y; // 0..15

    const float*  Asrc = x + (size_t)mTile * 128 * LAYER + (size_t)blk * BSZ;
    const __half* Bsrc = g_B + (size_t)blk * BSZ * BSZ;

    // per-thread load coords
    const int aRow = (tid * 4) >> 6;         // = f>>4 for f = tid*? ; recomputed below instead
    (void)aRow;

    wmma::fragment<wmma::accumulator, 16, 16, 16, float> acc[2][4];
    #pragma unroll
    for (int i = 0; i < 2; i++)
        #pragma unroll
        for (int j = 0; j < 4; j++) wmma::fill_fragment(acc[i][j], 0.0f);

    float4 aReg[4];

    // ---- prologue: A(0) -> regs, B(0) -> smem buf0 via cp.async ----
    #pragma unroll
    for (int i = 0; i < 4; i++) {
        int f = tid + i * 512;               // 2048 float4 ids
        int row = f >> 4, c4 = f & 15;
        aReg[i] = *reinterpret_cast<const float4*>(Asrc + (size_t)row * LAYER + c4 * 4);
    }
    #pragma unroll
    for (int i = 0; i < 4; i++) {
        int u = tid + i * 512;               // 2048 16B chunks
        int n = u >> 3, q = u & 7;
        uint32_t dst = sbase + SMB0 + (uint32_t)(n * LDB + q * 8) * 2;
        const __half* src = Bsrc + (size_t)n * BSZ + q * 8;
        asm volatile("cp.async.ca.shared.global [%0], [%1], 16;" :: "r"(dst), "l"(src) : "memory");
    }
    asm volatile("cp.async.commit_group;" ::: "memory");

    for (int c = 0; c < 4; c++) {
        const int buf = c & 1;
        __half* sA = reinterpret_cast<__half*>(smem + (buf ? SMA1 : SMA0));
        __half* sB = reinterpret_cast<__half*>(smem + (buf ? SMB1 : SMB0));

        // ---- convert A regs -> sA (fp16) ----
        #pragma unroll
        for (int i = 0; i < 4; i++) {
            int f = tid + i * 512;
            int row = f >> 4, c4 = f & 15;
            __half2 h01 = __floats2half2_rn(aReg[i].x, aReg[i].y);
            __half2 h23 = __floats2half2_rn(aReg[i].z, aReg[i].w);
            *reinterpret_cast<uint2*>(sA + row * LDA + c4 * 4) = make_uint2(h2u(h01), h2u(h23));
        }

        // ---- prefetch chunk c+1 (overlaps with MMA below) ----
        if (c < 3) {
            #pragma unroll
            for (int i = 0; i < 4; i++) {
                int f = tid + i * 512;
                int row = f >> 4, c4 = f & 15;
                aReg[i] = *reinterpret_cast<const float4*>(
                    Asrc + (size_t)row * LAYER + (c + 1) * KCH + c4 * 4);
            }
            uint32_t sbB = sbase + (((c + 1) & 1) ? SMB1 : SMB0);
            #pragma unroll
            for (int i = 0; i < 4; i++) {
                int u = tid + i * 512;
                int n = u >> 3, q = u & 7;
                uint32_t dst = sbB + (uint32_t)(n * LDB + q * 8) * 2;
                const __half* src = Bsrc + (size_t)n * BSZ + (c + 1) * KCH + q * 8;
                asm volatile("cp.async.ca.shared.global [%0], [%1], 16;" :: "r"(dst), "l"(src) : "memory");
            }
            asm volatile("cp.async.commit_group;" ::: "memory");
            asm volatile("cp.async.wait_group 1;" ::: "memory");   // chunk c's B done
        } else {
            asm volatile("cp.async.wait_group 0;" ::: "memory");
        }
        __syncthreads();

        // ---- MMA over buf ----
        #pragma unroll
        for (int ks = 0; ks < 4; ks++) {
            wmma::fragment<wmma::matrix_a, 16, 16, 16, __half, wmma::row_major> a0, a1;
            wmma::load_matrix_sync(a0, sA + (wm * 32)      * LDA + ks * 16, LDA);
            wmma::load_matrix_sync(a1, sA + (wm * 32 + 16) * LDA + ks * 16, LDA);
            #pragma unroll
            for (int j = 0; j < 4; j++) {
                wmma::fragment<wmma::matrix_b, 16, 16, 16, __half, wmma::col_major> b;
                wmma::load_matrix_sync(b, sB + ks * 16 + (wn * 64 + j * 16) * LDB, LDB);
                wmma::mma_sync(acc[0][j], a0, b, acc[0][j]);
                wmma::mma_sync(acc[1][j], a1, b, acc[1][j]);
            }
        }
        __syncthreads();
    }

    // ---- epilogue ----
    #pragma unroll
    for (int i = 0; i < 2; i++) {
        const int row0 = mTile * 128 + wm * 32 + i * 16;
        #pragma unroll
        for (int j = 0; j < 4; j++) {
            const int col0 = blk * BSZ + wn * 64 + j * 16;
            wmma::store_matrix_sync(out + (size_t)row0 * LAYER + col0, acc[i][j],
                                    LAYER, wmma::mem_row_major);
        }
    }
}

// ---------------- launch ----------------
extern "C" void kernel_launch(void* const* d_in, const int* in_sizes, int n_in,
                              void* d_out, int out_size) {
    const float* x      = (const float*)d_in[0];
    const float* blocks = (const float*)d_in[1];
    float* out = (float*)d_out;
    (void)in_sizes; (void)n_in; (void)out_size;

    cudaFuncSetAttribute(bd_hmma, cudaFuncAttributeMaxDynamicSharedMemorySize, SM_TOTAL);

    prep_B<<<dim3(8, NBLK), 256>>>(blocks);
    bd_hmma<<<dim3(NROWS / 128, NBLK), 512, SM_TOTAL>>>(x, out);
}